// round 1
// baseline (speedup 1.0000x reference)
#include <cuda_runtime.h>

#define LQ   9216
#define KD   144
#define CCH  16
#define HH   96
#define WW   96
#define BB   2
#define H2   192
#define W2   192
#define TOUT (BB*CCH*H2*W2)   /* 1179648 */
#define SOUT (BB*LQ)          /* 18432  */

__device__ float g_ref[BB*LQ*KD];
__device__ float g_lr [BB*LQ*KD];
__device__ float g_rnorm[BB*LQ];
__device__ int   g_S[BB*LQ];

// ---------------------------------------------------------------- unfold ----
__global__ __launch_bounds__(256) void unfold_kernel(
    const float* __restrict__ lrsr, const float* __restrict__ refsr) {
  int i = blockIdx.x * 256 + threadIdx.x;
  if (i >= BB*LQ*KD) return;
  int b  = i / (LQ*KD);
  int r  = i - b*(LQ*KD);
  int l  = r / KD;
  int f  = r - l*KD;
  int c  = f / 9;
  int k9 = f - c*9;
  int ki = k9 / 3;
  int kj = k9 - ki*3;
  int y  = l / WW;
  int x  = l - y*WW;
  int iy = y + ki - 1;
  int ix = x + kj - 1;
  bool ok = (iy >= 0) & (iy < HH) & (ix >= 0) & (ix < WW);
  int src = ((b*CCH + c)*HH + (ok ? iy : 0))*WW + (ok ? ix : 0);
  float lv = ok ? lrsr[src]  : 0.f;
  float rv = ok ? refsr[src] : 0.f;
  g_lr[i]  = lv;
  g_ref[i] = rv;
}

// ----------------------------------------------------------------- rnorm ----
__global__ __launch_bounds__(256) void rnorm_kernel() {
  int warp = (blockIdx.x * 256 + threadIdx.x) >> 5;
  int lane = threadIdx.x & 31;
  if (warp >= BB*LQ) return;
  const float* row = g_ref + (size_t)warp*KD;
  float ss = 0.f;
  #pragma unroll
  for (int j = 0; j < 5; j++) {
    int idx = lane + j*32;
    if (idx < KD) { float v = row[idx]; ss += v*v; }
  }
  #pragma unroll
  for (int o = 16; o; o >>= 1) ss += __shfl_xor_sync(0xffffffffu, ss, o);
  if (lane == 0) g_rnorm[warp] = 1.0f / fmaxf(sqrtf(ss), 1e-12f);
}

// -------------------------------------------------- argmax-GEMM (f32x2) ----
__device__ __forceinline__ void ffma2(unsigned long long &d,
                                      unsigned long long a,
                                      unsigned long long b) {
  asm("fma.rn.f32x2 %0, %1, %2, %0;" : "+l"(d) : "l"(a), "l"(b));
}
__device__ __forceinline__ unsigned long long dup2(float x) {
  unsigned long long r; unsigned int xi = __float_as_uint(x);
  asm("mov.b64 %0, {%1, %1};" : "=l"(r) : "r"(xi));
  return r;
}
__device__ __forceinline__ float lo32(unsigned long long v) {
  return __uint_as_float((unsigned)(v & 0xffffffffull));
}
__device__ __forceinline__ float hi32(unsigned long long v) {
  return __uint_as_float((unsigned)(v >> 32));
}

#define TMQ 64
#define TNR 128
#define KCC 8
#define NCHUNK (KD/KCC)   /* 18 */
#define NTILE  (LQ/TNR)   /* 72 */
#define ASTR   132        /* padded row stride, conflict-free */

__global__ __launch_bounds__(256) void argmax_kernel(
    float* __restrict__ out_tail, int write_tail) {
  __shared__ __align__(16) float Bs[KD*TMQ];        // lr tile, [k][q], 36864 B
  __shared__ __align__(16) float As[2*KCC*ASTR];    // ref chunks dbl-buf, 8448 B

  int tid = threadIdx.x;
  int tx = tid & 15, ty = tid >> 4;
  int b = blockIdx.y;
  int qBase = blockIdx.x * TMQ;
  const float* lr  = g_lr  + (size_t)b*LQ*KD;
  const float* ref = g_ref + (size_t)b*LQ*KD;
  const float* rn  = g_rnorm + b*LQ;

  // fill Bs transposed [k][q] once (reused for all 72 ref tiles)
  #pragma unroll
  for (int s = 0; s < 9; s++) {
    int idx = s*256 + tid;              // 0..2303
    int row = idx / 36;
    int kk  = (idx - row*36) * 4;
    float4 v = *reinterpret_cast<const float4*>(lr + (qBase+row)*KD + kk);
    Bs[(kk+0)*TMQ + row] = v.x;
    Bs[(kk+1)*TMQ + row] = v.y;
    Bs[(kk+2)*TMQ + row] = v.z;
    Bs[(kk+3)*TMQ + row] = v.w;
  }

  // prologue: stage chunk (tile 0, c 0)
  int lrow = tid >> 1;           // 0..127
  int lkk  = (tid & 1) * 4;      // 0 or 4
  {
    float4 pv = *reinterpret_cast<const float4*>(ref + (size_t)lrow*KD + lkk);
    float* dst = As + lkk*ASTR + lrow;
    dst[0*ASTR]=pv.x; dst[1*ASTR]=pv.y; dst[2*ASTR]=pv.z; dst[3*ASTR]=pv.w;
  }

  float bv[4]; int bi[4];
  #pragma unroll
  for (int i = 0; i < 4; i++) { bv[i] = -3.4e38f; bi[i] = 0; }

  int iter = 0;
  for (int t = 0; t < NTILE; t++) {
    int l0 = t * TNR;
    float4 rn0 = *reinterpret_cast<const float4*>(rn + l0 + tx*8);
    float4 rn1 = *reinterpret_cast<const float4*>(rn + l0 + tx*8 + 4);
    unsigned long long acc[4][4];
    #pragma unroll
    for (int i = 0; i < 4; i++)
      #pragma unroll
      for (int j = 0; j < 4; j++) acc[i][j] = 0ull;

    for (int c = 0; c < NCHUNK; c++) {
      __syncthreads();
      bool last = (t == NTILE-1) && (c == NCHUNK-1);
      float4 nv = make_float4(0.f,0.f,0.f,0.f);
      if (!last) {
        int nt = (c == NCHUNK-1) ? t+1 : t;
        int nc = (c == NCHUNK-1) ? 0   : c+1;
        nv = *reinterpret_cast<const float4*>(
            ref + ((size_t)nt*TNR + lrow)*KD + nc*KCC + lkk);
      }
      const float* Ab = As + (iter & 1) * (KCC*ASTR);
      #pragma unroll
      for (int k = 0; k < KCC; k++) {
        float4 bq = *reinterpret_cast<const float4*>(&Bs[(c*KCC + k)*TMQ + ty*4]);
        const ulonglong2* ap =
            reinterpret_cast<const ulonglong2*>(Ab + k*ASTR + tx*8);
        ulonglong2 A0 = ap[0];
        ulonglong2 A1 = ap[1];
        unsigned long long q0 = dup2(bq.x), q1 = dup2(bq.y);
        unsigned long long q2 = dup2(bq.z), q3 = dup2(bq.w);
        ffma2(acc[0][0], q0, A0.x); ffma2(acc[0][1], q0, A0.y);
        ffma2(acc[0][2], q0, A1.x); ffma2(acc[0][3], q0, A1.y);
        ffma2(acc[1][0], q1, A0.x); ffma2(acc[1][1], q1, A0.y);
        ffma2(acc[1][2], q1, A1.x); ffma2(acc[1][3], q1, A1.y);
        ffma2(acc[2][0], q2, A0.x); ffma2(acc[2][1], q2, A0.y);
        ffma2(acc[2][2], q2, A1.x); ffma2(acc[2][3], q2, A1.y);
        ffma2(acc[3][0], q3, A0.x); ffma2(acc[3][1], q3, A0.y);
        ffma2(acc[3][2], q3, A1.x); ffma2(acc[3][3], q3, A1.y);
      }
      if (!last) {
        float* dst = As + ((iter+1)&1)*(KCC*ASTR) + lkk*ASTR + lrow;
        dst[0*ASTR]=nv.x; dst[1*ASTR]=nv.y; dst[2*ASTR]=nv.z; dst[3*ASTR]=nv.w;
      }
      iter++;
    }

    // tile epilogue: scale by ref inv-norm, update running argmax
    float rnv[8] = {rn0.x,rn0.y,rn0.z,rn0.w,rn1.x,rn1.y,rn1.z,rn1.w};
    #pragma unroll
    for (int i = 0; i < 4; i++) {
      #pragma unroll
      for (int jj = 0; jj < 4; jj++) {
        int col = l0 + tx*8 + jj*2;
        float v0 = lo32(acc[i][jj]) * rnv[jj*2];
        float v1 = hi32(acc[i][jj]) * rnv[jj*2+1];
        if (v0 > bv[i]) { bv[i] = v0; bi[i] = col; }      // ascending idx:
        if (v1 > bv[i]) { bv[i] = v1; bi[i] = col + 1; }  // strict > keeps lowest
      }
    }
  }

  // cross-thread argmax reduce (reuse Bs)
  __syncthreads();
  float* redV = Bs;
  int*   redI = reinterpret_cast<int*>(Bs + 64*17);
  #pragma unroll
  for (int i = 0; i < 4; i++) {
    redV[(ty*4+i)*17 + tx] = bv[i];
    redI[(ty*4+i)*17 + tx] = bi[i];
  }
  __syncthreads();
  if (tid < 64) {
    float best = -3.4e38f; int bidx = 0x7fffffff;
    #pragma unroll
    for (int j = 0; j < 16; j++) {
      float v = redV[tid*17 + j]; int ii = redI[tid*17 + j];
      if (v > best || (v == best && ii < bidx)) { best = v; bidx = ii; }
    }
    g_S[b*LQ + qBase + tid] = bidx;
    if (write_tail) out_tail[b*LQ + qBase + tid] = (float)bidx;
  }
}

// ----------------------------------------------- gather + fold (fused) ------
__global__ __launch_bounds__(256) void fold_kernel(
    const float* __restrict__ org, float* __restrict__ out) {
  int b = blockIdx.z;
  int x = blockIdx.x*16 + threadIdx.x;
  int y = blockIdx.y*16 + threadIdx.y;
  int yp = y + 2, xp = x + 2;
  int myl = max(0, (yp-4)/2);
  int myh = min(95, yp >> 1);
  int mxl = max(0, (xp-4)/2);
  int mxh = min(95, xp >> 1);
  const int* Sb = g_S + b*LQ;

  int off[9];
  #pragma unroll
  for (int a = 0; a < 3; a++) {
    int my = myl + a;
    bool mok = (my <= myh);
    int myc = min(my, 95);
    int ki = yp - 2*my;
    #pragma unroll
    for (int e = 0; e < 3; e++) {
      int mx = mxl + e;
      bool xok = (mx <= mxh);
      int mxc = min(mx, 95);
      int kj = xp - 2*mx;
      int s = Sb[myc*96 + mxc];
      int sy = s / 96;
      int sx = s - sy*96;
      int gy = 2*sy + ki - 2;
      int gx = 2*sx + kj - 2;
      bool inb = mok & xok & (gy >= 0) & (gy < 192) & (gx >= 0) & (gx < 192);
      off[a*3 + e] = inb ? (gy*192 + gx) : -1;
    }
  }

  #pragma unroll 4
  for (int c = 0; c < 16; c++) {
    const float* oc = org + (size_t)((b*16 + c)*192)*192;
    float sum = 0.f;
    #pragma unroll
    for (int u = 0; u < 9; u++)
      if (off[u] >= 0) sum += oc[off[u]];
    out[((b*16 + c)*192 + y)*192 + x] = sum;
  }
}

// ------------------------------------------------------------------ host ----
extern "C" void kernel_launch(void* const* d_in, const int* in_sizes, int n_in,
                              void* d_out, int out_size) {
  (void)in_sizes; (void)n_in;
  const float* lrsr  = (const float*)d_in[0];
  const float* refsr = (const float*)d_in[1];
  const float* org   = (const float*)d_in[2];
  float* out = (float*)d_out;

  unfold_kernel<<<(BB*LQ*KD + 255)/256, 256>>>(lrsr, refsr);
  rnorm_kernel<<<(BB*LQ)/8, 256>>>();
  int write_tail = (out_size >= TOUT + SOUT) ? 1 : 0;
  argmax_kernel<<<dim3(LQ/TMQ, BB), 256>>>(out + TOUT, write_tail);
  fold_kernel<<<dim3(12, 12, BB), dim3(16, 16)>>>(org, out);
}

// round 6
// speedup vs baseline: 1.8477x; 1.8477x over previous
#include <cuda_runtime.h>
#include <cstdint>

#define LQ   9216
#define KD   144
#define KP   320              /* padded split K: [hi 0..143|0|lo 160..303|0] */
#define CCH  16
#define HH   96
#define WW   96
#define BB   2
#define TOUT (BB*CCH*192*192) /* 1179648 */
#define SOUT (BB*LQ)          /* 18432   */
#define NT   72               /* tiles of 128 patches */
#define NKB  10               /* k blocks of 32 floats */
#define TILE_F 40960          /* floats per packed tile image (10*4096) */

__device__ __align__(16) float g_raw_lr [BB*LQ*KP];
__device__ __align__(16) float g_raw_ref[BB*LQ*KP];
__device__ __align__(16) float g_A[BB*NT*TILE_F];
__device__ __align__(16) float g_B[BB*NT*TILE_F];
__device__ int g_S[BB*LQ];

// ------------------------------------------------------------ PTX helpers ---
__device__ __forceinline__ uint32_t smem_u32(const void* p) {
  uint32_t a;
  asm("{ .reg .u64 t; cvta.to.shared.u64 t, %1; cvt.u32.u64 %0, t; }"
      : "=r"(a) : "l"(p));
  return a;
}
__device__ __forceinline__ void mbar_init(uint32_t a, uint32_t cnt) {
  asm volatile("mbarrier.init.shared.b64 [%0], %1;" :: "r"(a), "r"(cnt) : "memory");
}
__device__ __forceinline__ void mbar_arrive(uint32_t a) {
  asm volatile("mbarrier.arrive.shared.b64 _, [%0];" :: "r"(a) : "memory");
}
__device__ __forceinline__ void mbar_wait(uint32_t a, uint32_t parity) {
  asm volatile(
      "{\n\t.reg .pred P;\n\t"
      "WL_%=:\n\t"
      "mbarrier.try_wait.parity.acquire.cta.shared::cta.b64 P, [%0], %1, 0x989680;\n\t"
      "@P bra.uni WD_%=;\n\t"
      "bra.uni WL_%=;\n\t"
      "WD_%=:\n\t}"
      :: "r"(a), "r"(parity) : "memory");
}
__device__ __forceinline__ void cp16(uint32_t dst, const void* src) {
  asm volatile("cp.async.cg.shared.global [%0], [%1], 16;"
               :: "r"(dst), "l"(src) : "memory");
}
__device__ __forceinline__ void cp_commit() {
  asm volatile("cp.async.commit_group;" ::: "memory");
}
__device__ __forceinline__ void cp_wait0() {
  asm volatile("cp.async.wait_group 0;" ::: "memory");
}
__device__ __forceinline__ void mma_tf32(float c[4], const uint32_t a[4],
                                         const uint32_t b[2]) {
  asm volatile(
      "mma.sync.aligned.m16n8k8.row.col.f32.tf32.tf32.f32 "
      "{%0,%1,%2,%3}, {%4,%5,%6,%7}, {%8,%9}, {%0,%1,%2,%3};"
      : "+f"(c[0]), "+f"(c[1]), "+f"(c[2]), "+f"(c[3])
      : "r"(a[0]), "r"(a[1]), "r"(a[2]), "r"(a[3]), "r"(b[0]), "r"(b[1]));
}

// ------------------------------------------------ prep: unfold+norm+split ---
__global__ __launch_bounds__(256) void prep_kernel(
    const float* __restrict__ lrsr, const float* __restrict__ refsr) {
  int gw   = (blockIdx.x * 256 + threadIdx.x) >> 5;
  int lane = threadIdx.x & 31;
  if (gw >= 2 * BB * LQ) return;
  int sel = (gw >= BB * LQ) ? 1 : 0;
  int r = gw - sel * BB * LQ;
  int b = r / LQ, l = r - b * LQ;
  int y = l / WW, x = l - y * WW;
  const float* src = (sel ? refsr : lrsr) + (size_t)b * CCH * HH * WW;

  float v[5];
  float ss = 0.f;
  #pragma unroll
  for (int j = 0; j < 5; j++) {
    int f = lane + j * 32;
    float val = 0.f;
    if (f < KD) {
      int c = f / 9, k9 = f - c * 9, ki = k9 / 3, kj = k9 - ki * 3;
      int iy = y + ki - 1, ix = x + kj - 1;
      if (iy >= 0 && iy < HH && ix >= 0 && ix < WW)
        val = src[(c * HH + iy) * WW + ix];
    }
    v[j] = val;
    ss += val * val;
  }
  float* dst;
  if (sel) {
    #pragma unroll
    for (int o = 16; o; o >>= 1) ss += __shfl_xor_sync(0xffffffffu, ss, o);
    float inv = 1.0f / fmaxf(sqrtf(ss), 1e-12f);
    #pragma unroll
    for (int j = 0; j < 5; j++) v[j] *= inv;
    dst = g_raw_ref;
  } else {
    dst = g_raw_lr;
  }
  dst += (size_t)r * KP;
  #pragma unroll
  for (int j = 0; j < 5; j++) {
    int f = lane + j * 32;     // 0..159 covers hi region; +160 covers lo region
    uint32_t hu, lu;
    asm("cvt.rna.tf32.f32 %0, %1;" : "=r"(hu) : "f"(v[j]));
    float lo_in = v[j] - __uint_as_float(hu);
    asm("cvt.rna.tf32.f32 %0, %1;" : "=r"(lu) : "f"(lo_in));
    dst[f]       = __uint_as_float(hu);
    dst[160 + f] = __uint_as_float(lu);
  }
}

// -------------------------------------- pack into mma-fragment layouts ------
// A quads (16B): (A[m][k], A[m+8][k], A[m][k+4], A[m+8][k+4])
// B pairs (8B):  (B[n][k], B[n][k+4])
__global__ __launch_bounds__(256) void pack_kernel() {
  int ti  = blockIdx.x;                 // b*72 + tile
  int isB = blockIdx.y;
  const float* raw = (isB ? g_raw_ref : g_raw_lr) + (size_t)ti * 128 * KP;
  float* dst = (isB ? g_B : g_A) + (size_t)ti * TILE_F;
  for (int o = threadIdx.x; o < TILE_F; o += 256) {
    int kb = o >> 12, oo = o & 4095;
    float val;
    if (isB) {
      int s = oo & 1, rest = oo >> 1;
      int a = rest & 3, n = (rest >> 2) & 127, k0g = rest >> 9;
      int k = kb * 32 + k0g * 8 + a + 4 * s;
      val = raw[(size_t)n * KP + k];
    } else {
      int rem = oo & 3, quad = oo >> 2;
      int a = quad & 3, g = (quad >> 2) & 7, mg = (quad >> 5) & 7,
          k0g = quad >> 8;
      int m = mg * 16 + g + 8 * (rem & 1);
      int k = kb * 32 + k0g * 8 + (rem >> 1) * 4 + a;
      val = raw[(size_t)m * KP + k];
    }
    dst[o] = val;
  }
}

// ------------------------------------------- argmax GEMM via mma.sync -------
#define SM_A_OFF 0         /* 163840 B: resident A tile image */
#define SM_B_OFF 163840    /* ring: 4 x 16384 B */
#define SM_MB    229376    /* mbarriers */
#define SMEM_TOTAL 229504

__global__ __launch_bounds__(256, 1) void argmax_mma(
    float* __restrict__ out_tail, int write_tail) {
  extern __shared__ __align__(16) char smem[];
  uint32_t sb = smem_u32(smem);
  int tid = threadIdx.x, wid = tid >> 5, lane = tid & 31;
  int cta = blockIdx.x;
  int b = cta / NT, qt = cta - b * NT;
  const float* Atile = g_A + (size_t)cta * TILE_F;
  const float* Bbase = g_B + (size_t)b * NT * TILE_F;

  uint32_t mb_full  = sb + SM_MB;       // 4 x 8B
  uint32_t mb_empty = sb + SM_MB + 32;  // 4 x 8B
  if (tid == 0) {
    for (int s = 0; s < 4; s++) {
      mbar_init(mb_full + 8 * s, 32);
      mbar_init(mb_empty + 8 * s, 128);
    }
  }
  // load resident A image (contiguous copy)
  for (int c = tid; c < TILE_F / 4; c += 256)
    cp16(sb + SM_A_OFF + c * 16, Atile + c * 4);
  cp_commit();
  cp_wait0();
  __syncthreads();

  if (wid >= 4) {
    // ---- producer warps: each owns one ring slot ----
    int pw = wid - 4;
    uint32_t slot = sb + SM_B_OFF + pw * 16384;
    for (int gblk = pw; gblk < NT * NKB; gblk += 4) {
      int u = gblk >> 2;
      mbar_wait(mb_empty + 8 * pw, (u & 1) ^ 1);
      const float* src = Bbase + (size_t)gblk * 4096;
      #pragma unroll 8
      for (int i = 0; i < 32; i++) {
        int c = i * 32 + lane;
        cp16(slot + c * 16, src + c * 4);
      }
      cp_commit();
      cp_wait0();
      mbar_arrive(mb_full + 8 * pw);
    }
  } else {
    // ---- compute warps: 2x2 grid of 64x64 tiles ----
    int wm = wid & 1, wn = wid >> 1;
    float C[4][8][4];
    float bestv[8];
    int besti[8];
    #pragma unroll
    for (int i = 0; i < 8; i++) { bestv[i] = -3.4e38f; besti[i] = 0; }

    uint32_t abase = sb + SM_A_OFF + (lane >> 2) * 64 + (lane & 3) * 16;
    uint32_t bbase = sb + SM_B_OFF + (wn * 64 + (lane >> 2)) * 32 + (lane & 3) * 8;

    for (int t = 0; t < NT; t++) {
      #pragma unroll
      for (int mf = 0; mf < 4; mf++)
        #pragma unroll
        for (int nf = 0; nf < 8; nf++)
          #pragma unroll
          for (int c = 0; c < 4; c++) C[mf][nf][c] = 0.f;

      for (int kb = 0; kb < NKB; kb++) {
        int gblk = t * NKB + kb, s = gblk & 3, u = gblk >> 2;
        mbar_wait(mb_full + 8 * s, u & 1);
        uint32_t bslot = bbase + s * 16384;
        int npass = (kb < 5) ? 2 : 1;
        int akb0 = (kb < 5) ? kb : kb - 5;
        #pragma unroll
        for (int k0g = 0; k0g < 4; k0g++) {
          uint32_t breg[8][2];
          #pragma unroll
          for (int nf = 0; nf < 8; nf++)
            asm volatile("ld.shared.v2.b32 {%0,%1}, [%2];"
                         : "=r"(breg[nf][0]), "=r"(breg[nf][1])
                         : "r"(bslot + k0g * 4096 + nf * 256));
          for (int pass = 0; pass < npass; pass++) {
            int akb = akb0 + pass * 5;
            uint32_t areg[4][4];
            #pragma unroll
            for (int mf = 0; mf < 4; mf++)
              asm volatile("ld.shared.v4.b32 {%0,%1,%2,%3}, [%4];"
                           : "=r"(areg[mf][0]), "=r"(areg[mf][1]),
                             "=r"(areg[mf][2]), "=r"(areg[mf][3])
                           : "r"(abase + akb * 16384 + k0g * 4096 +
                                 (wm * 4 + mf) * 512));
            #pragma unroll
            for (int mf = 0; mf < 4; mf++)
              #pragma unroll
              for (int nf = 0; nf < 8; nf++)
                mma_tf32(C[mf][nf], areg[mf], breg[nf]);
          }
        }
        mbar_arrive(mb_empty + 8 * s);
      }
      // running argmax (ascending n within slot; strict > keeps lowest idx)
      #pragma unroll
      for (int mf = 0; mf < 4; mf++) {
        #pragma unroll
        for (int h = 0; h < 2; h++) {
          int slot = mf * 2 + h;
          #pragma unroll
          for (int nf = 0; nf < 8; nf++) {
            #pragma unroll
            for (int cl = 0; cl < 2; cl++) {
              float vv = C[mf][nf][h * 2 + cl];
              int n = t * 128 + wn * 64 + nf * 8 + (lane & 3) * 2 + cl;
              if (vv > bestv[slot]) { bestv[slot] = vv; besti[slot] = n; }
            }
          }
        }
      }
    }
    // reduce across the 4 lanes of each quad (same m rows)
    #pragma unroll
    for (int slot = 0; slot < 8; slot++) {
      float v = bestv[slot];
      int i = besti[slot];
      #pragma unroll
      for (int off = 1; off <= 2; off <<= 1) {
        float ov = __shfl_xor_sync(0xffffffffu, v, off);
        int oi = __shfl_xor_sync(0xffffffffu, i, off);
        if (ov > v || (ov == v && oi < i)) { v = ov; i = oi; }
      }
      bestv[slot] = v; besti[slot] = i;
    }
    if ((lane & 3) == 0) {
      float* rv = reinterpret_cast<float*>(smem);
      int* ri = reinterpret_cast<int*>(smem + 1024);
      #pragma unroll
      for (int slot = 0; slot < 8; slot++) {
        int m_local = wm * 64 + (slot >> 1) * 16 + (slot & 1) * 8 + (lane >> 2);
        rv[wn * 128 + m_local] = bestv[slot];
        ri[wn * 128 + m_local] = besti[slot];
      }
    }
  }

  __syncthreads();
  if (tid < 128) {
    const float* rv = reinterpret_cast<const float*>(smem);
    const int* ri = reinterpret_cast<const int*>(smem + 1024);
    float v0 = rv[tid]; int i0 = ri[tid];
    float v1 = rv[128 + tid]; int i1 = ri[128 + tid];
    int bi = (v1 > v0 || (v1 == v0 && i1 < i0)) ? i1 : i0;
    g_S[b * LQ + qt * 128 + tid] = bi;
    if (write_tail) out_tail[b * LQ + qt * 128 + tid] = (float)bi;
  }
}

// ----------------------------------------------- gather + fold (fused) ------
__global__ __launch_bounds__(256) void fold_kernel(
    const float* __restrict__ org, float* __restrict__ out) {
  int b = blockIdx.z;
  int x = blockIdx.x * 16 + threadIdx.x;
  int y = blockIdx.y * 16 + threadIdx.y;
  int yp = y + 2, xp = x + 2;
  int myl = max(0, (yp - 4) / 2);
  int myh = min(95, yp >> 1);
  int mxl = max(0, (xp - 4) / 2);
  int mxh = min(95, xp >> 1);
  const int* Sb = g_S + b * LQ;

  int off[9];
  #pragma unroll
  for (int a = 0; a < 3; a++) {
    int my = myl + a;
    bool mok = (my <= myh);
    int myc = min(my, 95);
    int ki = yp - 2 * my;
    #pragma unroll
    for (int e = 0; e < 3; e++) {
      int mx = mxl + e;
      bool xok = (mx <= mxh);
      int mxc = min(mx, 95);
      int kj = xp - 2 * mx;
      int s = Sb[myc * 96 + mxc];
      int sy = s / 96;
      int sx = s - sy * 96;
      int gy = 2 * sy + ki - 2;
      int gx = 2 * sx + kj - 2;
      bool inb = mok & xok & (gy >= 0) & (gy < 192) & (gx >= 0) & (gx < 192);
      off[a * 3 + e] = inb ? (gy * 192 + gx) : -1;
    }
  }

  #pragma unroll 4
  for (int c = 0; c < 16; c++) {
    const float* oc = org + (size_t)((b * 16 + c) * 192) * 192;
    float sum = 0.f;
    #pragma unroll
    for (int u = 0; u < 9; u++)
      if (off[u] >= 0) sum += oc[off[u]];
    out[((b * 16 + c) * 192 + y) * 192 + x] = sum;
  }
}

// ------------------------------------------------------------------ host ----
extern "C" void kernel_launch(void* const* d_in, const int* in_sizes, int n_in,
                              void* d_out, int out_size) {
  (void)in_sizes; (void)n_in;
  const float* lrsr  = (const float*)d_in[0];
  const float* refsr = (const float*)d_in[1];
  const float* org   = (const float*)d_in[2];
  float* out = (float*)d_out;

  cudaFuncSetAttribute(argmax_mma, cudaFuncAttributeMaxDynamicSharedMemorySize,
                       SMEM_TOTAL);

  prep_kernel<<<(2 * BB * LQ * 32) / 256, 256>>>(lrsr, refsr);
  pack_kernel<<<dim3(BB * NT, 2), 256>>>();
  int write_tail = (out_size >= TOUT + SOUT) ? 1 : 0;
  argmax_mma<<<BB * NT, 256, SMEM_TOTAL>>>(out + TOUT, write_tail);
  fold_kernel<<<dim3(12, 12, BB), dim3(16, 16)>>>(org, out);
}

// round 8
// speedup vs baseline: 3.2313x; 1.7488x over previous
#include <cuda_runtime.h>
#include <cuda_fp16.h>
#include <cstdint>

#define LQ   9216
#define KD   144
#define CCH  16
#define HH   96
#define WW   96
#define BB   2
#define TOUT (BB*CCH*192*192) /* 1179648 */
#define SOUT (BB*LQ)          /* 18432   */
#define NT   72               /* tiles of 128 patches */
#define NKB  18               /* k16 blocks per tile: 9 hi + 9 lo */
#define TILE_U32 18432        /* packed u32 per tile image (18*1024) */

__device__ __align__(16) uint16_t g_raw_lr [BB*LQ*288];
__device__ __align__(16) uint16_t g_raw_ref[BB*LQ*288];
__device__ __align__(16) uint32_t g_A[BB*NT*TILE_U32];
__device__ __align__(16) uint32_t g_B[BB*NT*TILE_U32];
__device__ int g_S[BB*LQ];

// ------------------------------------------------------------ PTX helpers ---
__device__ __forceinline__ uint32_t smem_u32(const void* p) {
  uint32_t a;
  asm("{ .reg .u64 t; cvta.to.shared.u64 t, %1; cvt.u32.u64 %0, t; }"
      : "=r"(a) : "l"(p));
  return a;
}
__device__ __forceinline__ void mbar_init(uint32_t a, uint32_t cnt) {
  asm volatile("mbarrier.init.shared.b64 [%0], %1;" :: "r"(a), "r"(cnt) : "memory");
}
__device__ __forceinline__ void mbar_arrive(uint32_t a) {
  asm volatile("mbarrier.arrive.shared.b64 _, [%0];" :: "r"(a) : "memory");
}
__device__ __forceinline__ void mbar_wait(uint32_t a, uint32_t parity) {
  asm volatile(
      "{\n\t.reg .pred P;\n\t"
      "WL_%=:\n\t"
      "mbarrier.try_wait.parity.acquire.cta.shared::cta.b64 P, [%0], %1, 0x989680;\n\t"
      "@P bra.uni WD_%=;\n\t"
      "bra.uni WL_%=;\n\t"
      "WD_%=:\n\t}"
      :: "r"(a), "r"(parity) : "memory");
}
__device__ __forceinline__ void cp16(uint32_t dst, const void* src) {
  asm volatile("cp.async.cg.shared.global [%0], [%1], 16;"
               :: "r"(dst), "l"(src) : "memory");
}
__device__ __forceinline__ void cp_commit() {
  asm volatile("cp.async.commit_group;" ::: "memory");
}
__device__ __forceinline__ void cp_wait0() {
  asm volatile("cp.async.wait_group 0;" ::: "memory");
}
__device__ __forceinline__ void mma_f16(float c[4], const uint32_t a[4],
                                        const uint32_t b[2]) {
  asm volatile(
      "mma.sync.aligned.m16n8k16.row.col.f32.f16.f16.f32 "
      "{%0,%1,%2,%3}, {%4,%5,%6,%7}, {%8,%9}, {%0,%1,%2,%3};"
      : "+f"(c[0]), "+f"(c[1]), "+f"(c[2]), "+f"(c[3])
      : "r"(a[0]), "r"(a[1]), "r"(a[2]), "r"(a[3]), "r"(b[0]), "r"(b[1]));
}
// fp16 split via PTX (avoid header intrinsic dependence)
__device__ __forceinline__ void f16_split(float v, uint16_t& hi, uint16_t& lo) {
  uint16_t h;
  asm("cvt.rn.f16.f32 %0, %1;" : "=h"(h) : "f"(v));
  float hf;
  asm("cvt.f32.f16 %0, %1;" : "=f"(hf) : "h"(h));
  uint16_t l;
  asm("cvt.rn.f16.f32 %0, %1;" : "=h"(l) : "f"(v - hf));
  hi = h; lo = l;
}

// ---------------------------------------- prep: unfold + norm + fp16 split --
__global__ __launch_bounds__(256) void prep_kernel(
    const float* __restrict__ lrsr, const float* __restrict__ refsr) {
  int gw   = (blockIdx.x * 256 + threadIdx.x) >> 5;
  int lane = threadIdx.x & 31;
  if (gw >= 2 * BB * LQ) return;
  int sel = (gw >= BB * LQ) ? 1 : 0;
  int r = gw - sel * BB * LQ;
  int b = r / LQ, l = r - b * LQ;
  int y = l / WW, x = l - y * WW;
  const float* src = (sel ? refsr : lrsr) + (size_t)b * CCH * HH * WW;

  float v[5];
  float ss = 0.f;
  #pragma unroll
  for (int j = 0; j < 5; j++) {
    int f = lane + j * 32;
    float val = 0.f;
    if (f < KD) {
      int c = f / 9, k9 = f - c * 9, ki = k9 / 3, kj = k9 - ki * 3;
      int iy = y + ki - 1, ix = x + kj - 1;
      if (iy >= 0 && iy < HH && ix >= 0 && ix < WW)
        val = src[(c * HH + iy) * WW + ix];
    }
    v[j] = val;
    ss += val * val;
  }
  uint16_t* dst;
  if (sel) {
    #pragma unroll
    for (int o = 16; o; o >>= 1) ss += __shfl_xor_sync(0xffffffffu, ss, o);
    float inv = 1.0f / fmaxf(sqrtf(ss), 1e-12f);
    #pragma unroll
    for (int j = 0; j < 5; j++) v[j] *= inv;
    dst = g_raw_ref;
  } else {
    dst = g_raw_lr;
  }
  dst += (size_t)r * 288;
  #pragma unroll
  for (int j = 0; j < 5; j++) {
    int f = lane + j * 32;
    if (f < KD) {
      uint16_t h, lo;
      f16_split(v[j], h, lo);
      dst[f]       = h;
      dst[144 + f] = lo;
    }
  }
}

// ------------------------------- pack into m16n8k16 fragment layouts --------
// A block (4KB, one k16 step, 128 m): quad 16B per lane:
//   j=0:(m,2c|2c+1) j=1:(m+8,..) j=2:(m,2c+8|2c+9) j=3:(m+8,..)
// B block (4KB, one k16 step, 128 n): pair 8B per lane: j=0:k=2c, j=1:k=2c+8
__global__ __launch_bounds__(256) void pack_kernel() {
  int ti  = blockIdx.x;                  // b*NT + tile
  int isB = blockIdx.y;
  const uint32_t* raw32 = reinterpret_cast<const uint32_t*>(
      (isB ? g_raw_ref : g_raw_lr) + (size_t)ti * 128 * 288);
  uint4* dst = reinterpret_cast<uint4*>(
      (isB ? g_B : g_A) + (size_t)ti * TILE_U32);
  for (int o4 = threadIdx.x; o4 < TILE_U32 / 4; o4 += 256) {
    int kb = o4 >> 8, rr = o4 & 255;     // 256 uint4 per 4KB block
    uint4 val;
    if (isB) {
      int c2 = rr & 1, n = rr >> 1;      // c2: which c-pair, n: 0..127
      int q = n * 144 + kb * 8 + 2 * c2;
      val.x = raw32[q];     val.y = raw32[q + 4];
      val.z = raw32[q + 1]; val.w = raw32[q + 5];
    } else {
      int c = rr & 3, g = (rr >> 2) & 7, mg = rr >> 5;
      int m = mg * 16 + g;
      int q = kb * 8 + c;
      val.x = raw32[m * 144 + q];       val.y = raw32[(m + 8) * 144 + q];
      val.z = raw32[m * 144 + q + 4];   val.w = raw32[(m + 8) * 144 + q + 4];
    }
    dst[o4] = val;
  }
}

// ------------------------------------------- argmax GEMM via mma.sync -------
#define SM_A   0          /* 73728 B: resident A tile image (18 blocks) */
#define SM_B   73728      /* ring: 8 x 4096 B */
#define SM_MB  106496     /* mbarriers: 8 full + 8 empty */
#define SM_RV  106752     /* 1024 B reduce vals */
#define SM_RI  107776     /* 1024 B reduce idx  */
#define SMEM_TOTAL 108800

__global__ __launch_bounds__(256, 1) void argmax_mma(
    float* __restrict__ out_tail, int write_tail) {
  extern __shared__ __align__(16) char smem[];
  uint32_t sb = smem_u32(smem);
  int tid = threadIdx.x, wid = tid >> 5, lane = tid & 31;
  int cta = blockIdx.x;
  int b = cta / NT, qt = cta - b * NT;
  const uint32_t* Atile = g_A + (size_t)cta * TILE_U32;
  const uint32_t* Bbase = g_B + (size_t)b * NT * TILE_U32;

  uint32_t mb_full  = sb + SM_MB;        // 8 x 8B
  uint32_t mb_empty = sb + SM_MB + 64;   // 8 x 8B
  if (tid == 0) {
    for (int s = 0; s < 8; s++) {
      mbar_init(mb_full + 8 * s, 32);
      mbar_init(mb_empty + 8 * s, 128);
    }
  }
  // resident A image: contiguous 73728 B
  for (int c = tid; c < TILE_U32 / 4; c += 256)
    cp16(sb + SM_A + c * 16, Atile + c * 4);
  cp_commit();
  cp_wait0();
  __syncthreads();

  if (wid >= 4) {
    // ---- producers: 4 warps, gblk % 4 == pw, slot = gblk & 7 ----
    int pw = wid - 4;
    for (int gblk = pw; gblk < NT * NKB; gblk += 4) {
      int s = gblk & 7, u = gblk >> 3;
      mbar_wait(mb_empty + 8 * s, (u & 1) ^ 1);
      const uint32_t* src = Bbase + (size_t)gblk * 1024;
      uint32_t slot = sb + SM_B + s * 4096;
      #pragma unroll
      for (int i = 0; i < 8; i++) {
        int c = i * 32 + lane;
        cp16(slot + c * 16, src + c * 4);
      }
      cp_commit();
      cp_wait0();
      mbar_arrive(mb_full + 8 * s);
    }
  } else {
    // ---- compute warps: 2x2 grid of 64x64 warp tiles ----
    int wm = wid & 1, wn = wid >> 1;
    float C[4][8][4];
    float bestv[8];
    int besti[8];
    #pragma unroll
    for (int i = 0; i < 8; i++) { bestv[i] = -3.4e38f; besti[i] = 0; }

    uint32_t abase = sb + SM_A + (lane >> 2) * 64 + (lane & 3) * 16;
    uint32_t bbase = sb + SM_B + wn * 2048 + (lane >> 2) * 32 + (lane & 3) * 8;

    for (int t = 0; t < NT; t++) {
      #pragma unroll
      for (int mf = 0; mf < 4; mf++)
        #pragma unroll
        for (int nf = 0; nf < 8; nf++)
          #pragma unroll
          for (int c = 0; c < 4; c++) C[mf][nf][c] = 0.f;

      for (int kb = 0; kb < NKB; kb++) {
        int gblk = t * NKB + kb, s = gblk & 7, u = gblk >> 3;
        mbar_wait(mb_full + 8 * s, u & 1);
        uint32_t bslot = bbase + s * 4096;
        uint32_t breg[8][2];
        #pragma unroll
        for (int nf = 0; nf < 8; nf++)
          asm volatile("ld.shared.v2.b32 {%0,%1}, [%2];"
                       : "=r"(breg[nf][0]), "=r"(breg[nf][1])
                       : "r"(bslot + nf * 256));
        int npass = (kb < 9) ? 2 : 1;
        int ab0 = (kb < 9) ? kb : (kb - 9);
        for (int pass = 0; pass < npass; pass++) {
          int ab = ab0 + pass * 9;
          uint32_t areg[4][4];
          #pragma unroll
          for (int mf = 0; mf < 4; mf++)
            asm volatile("ld.shared.v4.b32 {%0,%1,%2,%3}, [%4];"
                         : "=r"(areg[mf][0]), "=r"(areg[mf][1]),
                           "=r"(areg[mf][2]), "=r"(areg[mf][3])
                         : "r"(abase + ab * 4096 + (wm * 4 + mf) * 512));
          #pragma unroll
          for (int mf = 0; mf < 4; mf++)
            #pragma unroll
            for (int nf = 0; nf < 8; nf++)
              mma_f16(C[mf][nf], areg[mf], breg[nf]);
        }
        mbar_arrive(mb_empty + 8 * s);
      }
      // running argmax (strict > keeps lowest index; n ascends in iteration)
      #pragma unroll
      for (int mf = 0; mf < 4; mf++) {
        #pragma unroll
        for (int h = 0; h < 2; h++) {
          int slot = mf * 2 + h;
          #pragma unroll
          for (int nf = 0; nf < 8; nf++) {
            #pragma unroll
            for (int cl = 0; cl < 2; cl++) {
              float vv = C[mf][nf][h * 2 + cl];
              int n = t * 128 + wn * 64 + nf * 8 + (lane & 3) * 2 + cl;
              if (vv > bestv[slot]) { bestv[slot] = vv; besti[slot] = n; }
            }
          }
        }
      }
    }
    // reduce across quad lanes (same m rows)
    #pragma unroll
    for (int slot = 0; slot < 8; slot++) {
      float v = bestv[slot];
      int i = besti[slot];
      #pragma unroll
      for (int off = 1; off <= 2; off <<= 1) {
        float ov = __shfl_xor_sync(0xffffffffu, v, off);
        int oi = __shfl_xor_sync(0xffffffffu, i, off);
        if (ov > v || (ov == v && oi < i)) { v = ov; i = oi; }
      }
      bestv[slot] = v; besti[slot] = i;
    }
    if ((lane & 3) == 0) {
      float* rv = reinterpret_cast<float*>(smem + SM_RV);
      int* ri = reinterpret_cast<int*>(smem + SM_RI);
      #pragma unroll
      for (int slot = 0; slot < 8; slot++) {
        int m_local = wm * 64 + (slot >> 1) * 16 + (slot & 1) * 8 + (lane >> 2);
        rv[wn * 128 + m_local] = bestv[slot];
        ri[wn * 128 + m_local] = besti[slot];
      }
    }
  }

  __syncthreads();
  if (tid < 128) {
    const float* rv = reinterpret_cast<const float*>(smem + SM_RV);
    const int* ri = reinterpret_cast<const int*>(smem + SM_RI);
    float v0 = rv[tid]; int i0 = ri[tid];
    float v1 = rv[128 + tid]; int i1 = ri[128 + tid];
    int bi = (v1 > v0 || (v1 == v0 && i1 < i0)) ? i1 : i0;
    g_S[b * LQ + qt * 128 + tid] = bi;
    if (write_tail) out_tail[b * LQ + qt * 128 + tid] = (float)bi;
  }
}

// ----------------------------------------------- gather + fold (fused) ------
__global__ __launch_bounds__(256) void fold_kernel(
    const float* __restrict__ org, float* __restrict__ out) {
  int b = blockIdx.z;
  int x = blockIdx.x * 16 + threadIdx.x;
  int y = blockIdx.y * 16 + threadIdx.y;
  int yp = y + 2, xp = x + 2;
  int myl = max(0, (yp - 4) / 2);
  int myh = min(95, yp >> 1);
  int mxl = max(0, (xp - 4) / 2);
  int mxh = min(95, xp >> 1);
  const int* Sb = g_S + b * LQ;

  int off[9];
  #pragma unroll
  for (int a = 0; a < 3; a++) {
    int my = myl + a;
    bool mok = (my <= myh);
    int myc = min(my, 95);
    int ki = yp - 2 * my;
    #pragma unroll
    for (int e = 0; e < 3; e++) {
      int mx = mxl + e;
      bool xok = (mx <= mxh);
      int mxc = min(mx, 95);
      int kj = xp - 2 * mx;
      int s = Sb[myc * 96 + mxc];
      int sy = s / 96;
      int sx = s - sy * 96;
      int gy = 2 * sy + ki - 2;
      int gx = 2 * sx + kj - 2;
      bool inb = mok & xok & (gy >= 0) & (gy < 192) & (gx >= 0) & (gx < 192);
      off[a * 3 + e] = inb ? (gy * 192 + gx) : -1;
    }
  }

  #pragma unroll 4
  for (int c = 0; c < 16; c++) {
    const float* oc = org + (size_t)((b * 16 + c) * 192) * 192;
    float sum = 0.f;
    #pragma unroll
    for (int u = 0; u < 9; u++)
      if (off[u] >= 0) sum += oc[off[u]];
    out[((b * 16 + c) * 192 + y) * 192 + x] = sum;
  }
}

// ------------------------------------------------------------------ host ----
extern "C" void kernel_launch(void* const* d_in, const int* in_sizes, int n_in,
                              void* d_out, int out_size) {
  (void)in_sizes; (void)n_in;
  const float* lrsr  = (const float*)d_in[0];
  const float* refsr = (const float*)d_in[1];
  const float* org   = (const float*)d_in[2];
  float* out = (float*)d_out;

  cudaFuncSetAttribute(argmax_mma, cudaFuncAttributeMaxDynamicSharedMemorySize,
                       SMEM_TOTAL);

  prep_kernel<<<(2 * BB * LQ * 32) / 256, 256>>>(lrsr, refsr);
  pack_kernel<<<dim3(BB * NT, 2), 256>>>();
  int write_tail = (out_size >= TOUT + SOUT) ? 1 : 0;
  argmax_mma<<<BB * NT, 256, SMEM_TOTAL>>>(out + TOUT, write_tail);
  fold_kernel<<<dim3(12, 12, BB), dim3(16, 16)>>>(org, out);
}

// round 9
// speedup vs baseline: 4.3063x; 1.3327x over previous
#include <cuda_runtime.h>
#include <cuda_fp16.h>
#include <cstdint>

#define LQ   9216
#define KD   144
#define CCH  16
#define HH   96
#define WW   96
#define BB   2
#define TOUT (BB*CCH*192*192) /* 1179648 */
#define SOUT (BB*LQ)          /* 18432   */
#define NT   72               /* tiles of 128 patches */
#define NKB  18               /* k16 blocks per tile: 9 hi + 9 lo */
#define TILE_U32 18432        /* packed u32 per tile image (18*1024) */

__device__ __align__(16) uint16_t g_raw_lr [BB*LQ*288];
__device__ __align__(16) uint16_t g_raw_ref[BB*LQ*288];
__device__ __align__(16) uint32_t g_A[BB*NT*TILE_U32];
__device__ __align__(16) uint32_t g_B[BB*NT*TILE_U32];
__device__ int g_S[BB*LQ];

// ------------------------------------------------------------ PTX helpers ---
__device__ __forceinline__ uint32_t smem_u32(const void* p) {
  uint32_t a;
  asm("{ .reg .u64 t; cvta.to.shared.u64 t, %1; cvt.u32.u64 %0, t; }"
      : "=r"(a) : "l"(p));
  return a;
}
__device__ __forceinline__ void mbar_init(uint32_t a, uint32_t cnt) {
  asm volatile("mbarrier.init.shared.b64 [%0], %1;" :: "r"(a), "r"(cnt) : "memory");
}
__device__ __forceinline__ void mbar_arrive(uint32_t a) {
  asm volatile("mbarrier.arrive.shared.b64 _, [%0];" :: "r"(a) : "memory");
}
__device__ __forceinline__ void mbar_wait(uint32_t a, uint32_t parity) {
  asm volatile(
      "{\n\t.reg .pred P;\n\t"
      "WL_%=:\n\t"
      "mbarrier.try_wait.parity.acquire.cta.shared::cta.b64 P, [%0], %1, 0x989680;\n\t"
      "@P bra.uni WD_%=;\n\t"
      "bra.uni WL_%=;\n\t"
      "WD_%=:\n\t}"
      :: "r"(a), "r"(parity) : "memory");
}
__device__ __forceinline__ void cp16(uint32_t dst, const void* src) {
  asm volatile("cp.async.cg.shared.global [%0], [%1], 16;"
               :: "r"(dst), "l"(src) : "memory");
}
__device__ __forceinline__ void cp_commit() {
  asm volatile("cp.async.commit_group;" ::: "memory");
}
__device__ __forceinline__ void cp_wait0() {
  asm volatile("cp.async.wait_group 0;" ::: "memory");
}
__device__ __forceinline__ void mma_f16(float c[4], const uint32_t a[4],
                                        const uint32_t b[2]) {
  asm volatile(
      "mma.sync.aligned.m16n8k16.row.col.f32.f16.f16.f32 "
      "{%0,%1,%2,%3}, {%4,%5,%6,%7}, {%8,%9}, {%0,%1,%2,%3};"
      : "+f"(c[0]), "+f"(c[1]), "+f"(c[2]), "+f"(c[3])
      : "r"(a[0]), "r"(a[1]), "r"(a[2]), "r"(a[3]), "r"(b[0]), "r"(b[1]));
}
// fp16 split via PTX (avoid header intrinsic dependence)
__device__ __forceinline__ void f16_split(float v, uint16_t& hi, uint16_t& lo) {
  uint16_t h;
  asm("cvt.rn.f16.f32 %0, %1;" : "=h"(h) : "f"(v));
  float hf;
  asm("cvt.f32.f16 %0, %1;" : "=f"(hf) : "h"(h));
  uint16_t l;
  asm("cvt.rn.f16.f32 %0, %1;" : "=h"(l) : "f"(v - hf));
  hi = h; lo = l;
}

// ---------------------------------------- prep: unfold + norm + fp16 split --
__global__ __launch_bounds__(256) void prep_kernel(
    const float* __restrict__ lrsr, const float* __restrict__ refsr) {
  int gw   = (blockIdx.x * 256 + threadIdx.x) >> 5;
  int lane = threadIdx.x & 31;
  if (gw >= 2 * BB * LQ) return;
  int sel = (gw >= BB * LQ) ? 1 : 0;
  int r = gw - sel * BB * LQ;
  int b = r / LQ, l = r - b * LQ;
  int y = l / WW, x = l - y * WW;
  const float* src = (sel ? refsr : lrsr) + (size_t)b * CCH * HH * WW;

  float v[5];
  float ss = 0.f;
  #pragma unroll
  for (int j = 0; j < 5; j++) {
    int f = lane + j * 32;
    float val = 0.f;
    if (f < KD) {
      int c = f / 9, k9 = f - c * 9, ki = k9 / 3, kj = k9 - ki * 3;
      int iy = y + ki - 1, ix = x + kj - 1;
      if (iy >= 0 && iy < HH && ix >= 0 && ix < WW)
        val = src[(c * HH + iy) * WW + ix];
    }
    v[j] = val;
    ss += val * val;
  }
  uint16_t* dst;
  if (sel) {
    #pragma unroll
    for (int o = 16; o; o >>= 1) ss += __shfl_xor_sync(0xffffffffu, ss, o);
    float inv = 1.0f / fmaxf(sqrtf(ss), 1e-12f);
    #pragma unroll
    for (int j = 0; j < 5; j++) v[j] *= inv;
    dst = g_raw_ref;
  } else {
    dst = g_raw_lr;
  }
  dst += (size_t)r * 288;
  #pragma unroll
  for (int j = 0; j < 5; j++) {
    int f = lane + j * 32;
    if (f < KD) {
      uint16_t h, lo;
      f16_split(v[j], h, lo);
      dst[f]       = h;
      dst[144 + f] = lo;
    }
  }
}

// ------------------------------- pack into m16n8k16 fragment layouts --------
__global__ __launch_bounds__(256) void pack_kernel() {
  int ti  = blockIdx.x;                  // b*NT + tile
  int isB = blockIdx.y;
  const uint32_t* raw32 = reinterpret_cast<const uint32_t*>(
      (isB ? g_raw_ref : g_raw_lr) + (size_t)ti * 128 * 288);
  uint4* dst = reinterpret_cast<uint4*>(
      (isB ? g_B : g_A) + (size_t)ti * TILE_U32);
  for (int o4 = threadIdx.x; o4 < TILE_U32 / 4; o4 += 256) {
    int kb = o4 >> 8, rr = o4 & 255;     // 256 uint4 per 4KB block
    uint4 val;
    if (isB) {
      int c2 = rr & 1, n = rr >> 1;
      int q = n * 144 + kb * 8 + 2 * c2;
      val.x = raw32[q];     val.y = raw32[q + 4];
      val.z = raw32[q + 1]; val.w = raw32[q + 5];
    } else {
      int c = rr & 3, g = (rr >> 2) & 7, mg = rr >> 5;
      int m = mg * 16 + g;
      int q = kb * 8 + c;
      val.x = raw32[m * 144 + q];       val.y = raw32[(m + 8) * 144 + q];
      val.z = raw32[m * 144 + q + 4];   val.w = raw32[(m + 8) * 144 + q + 4];
    }
    dst[o4] = val;
  }
}

// ------------------------------------------- argmax GEMM via mma.sync -------
#define SM_A   0          /* 73728 B: resident A tile image (18 blocks) */
#define SM_B   73728      /* ring: 8 x 4096 B */
#define SM_MB  106496     /* mbarriers: 8 full + 8 empty */
#define SM_RV  106752     /* 2048 B reduce vals (4 x 128) */
#define SM_RI  108800     /* 2048 B reduce idx  */
#define SMEM_TOTAL 110848

__global__ __launch_bounds__(384, 1) void argmax_mma(
    float* __restrict__ out_tail, int write_tail) {
  extern __shared__ __align__(16) char smem[];
  uint32_t sb = smem_u32(smem);
  int tid = threadIdx.x, wid = tid >> 5, lane = tid & 31;
  int cta = blockIdx.x;
  int b = cta / NT, qt = cta - b * NT;
  const uint32_t* Atile = g_A + (size_t)cta * TILE_U32;
  const uint32_t* Bbase = g_B + (size_t)b * NT * TILE_U32;

  uint32_t mb_full  = sb + SM_MB;        // 8 x 8B
  uint32_t mb_empty = sb + SM_MB + 64;   // 8 x 8B
  if (tid == 0) {
    for (int s = 0; s < 8; s++) {
      mbar_init(mb_full + 8 * s, 32);
      mbar_init(mb_empty + 8 * s, 256);  // 8 compute warps x 32 lanes
    }
  }
  // resident A image: contiguous 73728 B
  for (int c = tid; c < TILE_U32 / 4; c += 384)
    cp16(sb + SM_A + c * 16, Atile + c * 4);
  cp_commit();
  cp_wait0();
  __syncthreads();

  if (wid >= 8) {
    // ---- producers: 4 warps, gblk % 4 == pw, slot = gblk & 7 ----
    int pw = wid - 8;
    for (int gblk = pw; gblk < NT * NKB; gblk += 4) {
      int s = gblk & 7, u = gblk >> 3;
      mbar_wait(mb_empty + 8 * s, (u & 1) ^ 1);
      const uint32_t* src = Bbase + (size_t)gblk * 1024;
      uint32_t slot = sb + SM_B + s * 4096;
      #pragma unroll
      for (int i = 0; i < 8; i++) {
        int c = i * 32 + lane;
        cp16(slot + c * 16, src + c * 4);
      }
      cp_commit();
      cp_wait0();
      mbar_arrive(mb_full + 8 * s);
    }
  } else {
    // ---- compute warps: 2x4 grid of 64x32 warp tiles (2 warps / SMSP) ----
    int wm = wid & 1, wn = (wid >> 1) & 3;
    float C[4][4][4];
    float bestv[8];
    int besti[8];
    #pragma unroll
    for (int i = 0; i < 8; i++) { bestv[i] = -3.4e38f; besti[i] = 0; }

    uint32_t abase = sb + SM_A + (lane >> 2) * 64 + (lane & 3) * 16;
    uint32_t bbase = sb + SM_B + wn * 1024 + (lane >> 2) * 32 + (lane & 3) * 8;

    for (int t = 0; t < NT; t++) {
      #pragma unroll
      for (int mf = 0; mf < 4; mf++)
        #pragma unroll
        for (int nf = 0; nf < 4; nf++)
          #pragma unroll
          for (int c = 0; c < 4; c++) C[mf][nf][c] = 0.f;

      for (int kb = 0; kb < NKB; kb++) {
        int gblk = t * NKB + kb, s = gblk & 7, u = gblk >> 3;
        mbar_wait(mb_full + 8 * s, u & 1);
        uint32_t bslot = bbase + s * 4096;
        uint32_t breg[4][2];
        #pragma unroll
        for (int nf = 0; nf < 4; nf++)
          asm volatile("ld.shared.v2.b32 {%0,%1}, [%2];"
                       : "=r"(breg[nf][0]), "=r"(breg[nf][1])
                       : "r"(bslot + nf * 256));
        int npass = (kb < 9) ? 2 : 1;
        int ab0 = (kb < 9) ? kb : (kb - 9);
        for (int pass = 0; pass < npass; pass++) {
          int ab = ab0 + pass * 9;
          uint32_t areg[4][4];
          #pragma unroll
          for (int mf = 0; mf < 4; mf++)
            asm volatile("ld.shared.v4.b32 {%0,%1,%2,%3}, [%4];"
                         : "=r"(areg[mf][0]), "=r"(areg[mf][1]),
                           "=r"(areg[mf][2]), "=r"(areg[mf][3])
                         : "r"(abase + ab * 4096 + (wm * 4 + mf) * 512));
          #pragma unroll
          for (int mf = 0; mf < 4; mf++)
            #pragma unroll
            for (int nf = 0; nf < 4; nf++)
              mma_f16(C[mf][nf], areg[mf], breg[nf]);
        }
        mbar_arrive(mb_empty + 8 * s);
      }
      // running argmax (strict > keeps lowest index; n ascends in iteration)
      #pragma unroll
      for (int mf = 0; mf < 4; mf++) {
        #pragma unroll
        for (int h = 0; h < 2; h++) {
          int slot = mf * 2 + h;
          #pragma unroll
          for (int nf = 0; nf < 4; nf++) {
            #pragma unroll
            for (int cl = 0; cl < 2; cl++) {
              float vv = C[mf][nf][h * 2 + cl];
              int n = t * 128 + wn * 32 + nf * 8 + (lane & 3) * 2 + cl;
              if (vv > bestv[slot]) { bestv[slot] = vv; besti[slot] = n; }
            }
          }
        }
      }
    }
    // reduce across quad lanes (same m rows)
    #pragma unroll
    for (int slot = 0; slot < 8; slot++) {
      float v = bestv[slot];
      int i = besti[slot];
      #pragma unroll
      for (int off = 1; off <= 2; off <<= 1) {
        float ov = __shfl_xor_sync(0xffffffffu, v, off);
        int oi = __shfl_xor_sync(0xffffffffu, i, off);
        if (ov > v || (ov == v && oi < i)) { v = ov; i = oi; }
      }
      bestv[slot] = v; besti[slot] = i;
    }
    if ((lane & 3) == 0) {
      float* rv = reinterpret_cast<float*>(smem + SM_RV);
      int* ri = reinterpret_cast<int*>(smem + SM_RI);
      #pragma unroll
      for (int slot = 0; slot < 8; slot++) {
        int m_local = wm * 64 + (slot >> 1) * 16 + (slot & 1) * 8 + (lane >> 2);
        rv[wn * 128 + m_local] = bestv[slot];
        ri[wn * 128 + m_local] = besti[slot];
      }
    }
  }

  __syncthreads();
  if (tid < 128) {
    const float* rv = reinterpret_cast<const float*>(smem + SM_RV);
    const int* ri = reinterpret_cast<const int*>(smem + SM_RI);
    float best = -3.4e38f; int bi = 0x7fffffff;
    #pragma unroll
    for (int wn = 0; wn < 4; wn++) {
      float v = rv[wn * 128 + tid];
      int i = ri[wn * 128 + tid];
      if (v > best || (v == best && i < bi)) { best = v; bi = i; }
    }
    g_S[b * LQ + qt * 128 + tid] = bi;
    if (write_tail) out_tail[b * LQ + qt * 128 + tid] = (float)bi;
  }
}

// ----------------------------------------------- gather + fold (fused) ------
__global__ __launch_bounds__(256) void fold_kernel(
    const float* __restrict__ org, float* __restrict__ out) {
  int b = blockIdx.z;
  int x = blockIdx.x * 16 + threadIdx.x;
  int y = blockIdx.y * 16 + threadIdx.y;
  int yp = y + 2, xp = x + 2;
  int myl = max(0, (yp - 4) / 2);
  int myh = min(95, yp >> 1);
  int mxl = max(0, (xp - 4) / 2);
  int mxh = min(95, xp >> 1);
  const int* Sb = g_S + b * LQ;

  int off[9];
  #pragma unroll
  for (int a = 0; a < 3; a++) {
    int my = myl + a;
    bool mok = (my <= myh);
    int myc = min(my, 95);
    int ki = yp - 2 * my;
    #pragma unroll
    for (int e = 0; e < 3; e++) {
      int mx = mxl + e;
      bool xok = (mx <= mxh);
      int mxc = min(mx, 95);
      int kj = xp - 2 * mx;
      int s = Sb[myc * 96 + mxc];
      int sy = s / 96;
      int sx = s - sy * 96;
      int gy = 2 * sy + ki - 2;
      int gx = 2 * sx + kj - 2;
      bool inb = mok & xok & (gy >= 0) & (gy < 192) & (gx >= 0) & (gx < 192);
      off[a * 3 + e] = inb ? (gy * 192 + gx) : -1;
    }
  }

  #pragma unroll 4
  for (int c = 0; c < 16; c++) {
    const float* oc = org + (size_t)((b * 16 + c) * 192) * 192;
    float sum = 0.f;
    #pragma unroll
    for (int u = 0; u < 9; u++)
      if (off[u] >= 0) sum += oc[off[u]];
    out[((b * 16 + c) * 192 + y) * 192 + x] = sum;
  }
}

// ------------------------------------------------------------------ host ----
extern "C" void kernel_launch(void* const* d_in, const int* in_sizes, int n_in,
                              void* d_out, int out_size) {
  (void)in_sizes; (void)n_in;
  const float* lrsr  = (const float*)d_in[0];
  const float* refsr = (const float*)d_in[1];
  const float* org   = (const float*)d_in[2];
  float* out = (float*)d_out;

  cudaFuncSetAttribute(argmax_mma, cudaFuncAttributeMaxDynamicSharedMemorySize,
                       SMEM_TOTAL);

  prep_kernel<<<(2 * BB * LQ * 32) / 256, 256>>>(lrsr, refsr);
  pack_kernel<<<dim3(BB * NT, 2), 256>>>();
  int write_tail = (out_size >= TOUT + SOUT) ? 1 : 0;
  argmax_mma<<<BB * NT, 384, SMEM_TOTAL>>>(out + TOUT, write_tail);
  fold_kernel<<<dim3(12, 12, BB), dim3(16, 16)>>>(org, out);
}

// round 10
// speedup vs baseline: 4.3806x; 1.0173x over previous
#include <cuda_runtime.h>
#include <cuda_fp16.h>
#include <cstdint>

#define LQ   9216
#define KD   144
#define CCH  16
#define HH   96
#define WW   96
#define BB   2
#define TOUT (BB*CCH*192*192) /* 1179648 */
#define SOUT (BB*LQ)          /* 18432   */
#define NT   72               /* tiles of 128 patches */
#define NKB  18               /* k16 blocks per tile: 9 hi + 9 lo */
#define TILE_U32 18432        /* packed u32 per tile image (18*1024) */

__device__ __align__(16) uint16_t g_raw_lr [BB*LQ*288];
__device__ __align__(16) uint16_t g_raw_ref[BB*LQ*288];
__device__ __align__(16) uint32_t g_A[BB*NT*TILE_U32];
__device__ __align__(16) uint32_t g_B[BB*NT*TILE_U32];
__device__ int g_S[BB*LQ];

// ------------------------------------------------------------ PTX helpers ---
__device__ __forceinline__ uint32_t smem_u32(const void* p) {
  uint32_t a;
  asm("{ .reg .u64 t; cvta.to.shared.u64 t, %1; cvt.u32.u64 %0, t; }"
      : "=r"(a) : "l"(p));
  return a;
}
__device__ __forceinline__ void mbar_init(uint32_t a, uint32_t cnt) {
  asm volatile("mbarrier.init.shared.b64 [%0], %1;" :: "r"(a), "r"(cnt) : "memory");
}
__device__ __forceinline__ void mbar_arrive(uint32_t a) {
  asm volatile("mbarrier.arrive.shared.b64 _, [%0];" :: "r"(a) : "memory");
}
__device__ __forceinline__ void mbar_wait(uint32_t a, uint32_t parity) {
  asm volatile(
      "{\n\t.reg .pred P;\n\t"
      "WL_%=:\n\t"
      "mbarrier.try_wait.parity.acquire.cta.shared::cta.b64 P, [%0], %1, 0x989680;\n\t"
      "@P bra.uni WD_%=;\n\t"
      "bra.uni WL_%=;\n\t"
      "WD_%=:\n\t}"
      :: "r"(a), "r"(parity) : "memory");
}
__device__ __forceinline__ void cp16(uint32_t dst, const void* src) {
  asm volatile("cp.async.cg.shared.global [%0], [%1], 16;"
               :: "r"(dst), "l"(src) : "memory");
}
__device__ __forceinline__ void cp_commit() {
  asm volatile("cp.async.commit_group;" ::: "memory");
}
__device__ __forceinline__ void cp_wait0() {
  asm volatile("cp.async.wait_group 0;" ::: "memory");
}
// fp32-accum HMMA (main hi*hi term)
__device__ __forceinline__ void mma_f16(float c[4], const uint32_t a[4],
                                        const uint32_t b[2]) {
  asm volatile(
      "mma.sync.aligned.m16n8k16.row.col.f32.f16.f16.f32 "
      "{%0,%1,%2,%3}, {%4,%5,%6,%7}, {%8,%9}, {%0,%1,%2,%3};"
      : "+f"(c[0]), "+f"(c[1]), "+f"(c[2]), "+f"(c[3])
      : "r"(a[0]), "r"(a[1]), "r"(a[2]), "r"(a[3]), "r"(b[0]), "r"(b[1]));
}
// fp16-accum HMMA (tiny cross-compensation terms)
__device__ __forceinline__ void mma_f16acc(uint32_t c[2], const uint32_t a[4],
                                           const uint32_t b[2]) {
  asm volatile(
      "mma.sync.aligned.m16n8k16.row.col.f16.f16.f16.f16 "
      "{%0,%1}, {%2,%3,%4,%5}, {%6,%7}, {%0,%1};"
      : "+r"(c[0]), "+r"(c[1])
      : "r"(a[0]), "r"(a[1]), "r"(a[2]), "r"(a[3]), "r"(b[0]), "r"(b[1]));
}
__device__ __forceinline__ float f16bits_to_f32(uint32_t bits) {
  float f;
  asm("{ .reg .b16 h; cvt.u16.u32 h, %1; cvt.f32.f16 %0, h; }"
      : "=f"(f) : "r"(bits));
  return f;
}
// fp16 split via PTX (avoid header intrinsic dependence)
__device__ __forceinline__ void f16_split(float v, uint16_t& hi, uint16_t& lo) {
  uint16_t h;
  asm("cvt.rn.f16.f32 %0, %1;" : "=h"(h) : "f"(v));
  float hf;
  asm("cvt.f32.f16 %0, %1;" : "=f"(hf) : "h"(h));
  uint16_t l;
  asm("cvt.rn.f16.f32 %0, %1;" : "=h"(l) : "f"(v - hf));
  hi = h; lo = l;
}

// ---------------------------------------- prep: unfold + norm + fp16 split --
__global__ __launch_bounds__(256) void prep_kernel(
    const float* __restrict__ lrsr, const float* __restrict__ refsr) {
  int gw   = (blockIdx.x * 256 + threadIdx.x) >> 5;
  int lane = threadIdx.x & 31;
  if (gw >= 2 * BB * LQ) return;
  int sel = (gw >= BB * LQ) ? 1 : 0;
  int r = gw - sel * BB * LQ;
  int b = r / LQ, l = r - b * LQ;
  int y = l / WW, x = l - y * WW;
  const float* src = (sel ? refsr : lrsr) + (size_t)b * CCH * HH * WW;

  float v[5];
  float ss = 0.f;
  #pragma unroll
  for (int j = 0; j < 5; j++) {
    int f = lane + j * 32;
    float val = 0.f;
    if (f < KD) {
      int c = f / 9, k9 = f - c * 9, ki = k9 / 3, kj = k9 - ki * 3;
      int iy = y + ki - 1, ix = x + kj - 1;
      if (iy >= 0 && iy < HH && ix >= 0 && ix < WW)
        val = src[(c * HH + iy) * WW + ix];
    }
    v[j] = val;
    ss += val * val;
  }
  uint16_t* dst;
  if (sel) {
    #pragma unroll
    for (int o = 16; o; o >>= 1) ss += __shfl_xor_sync(0xffffffffu, ss, o);
    float inv = 1.0f / fmaxf(sqrtf(ss), 1e-12f);
    #pragma unroll
    for (int j = 0; j < 5; j++) v[j] *= inv;
    dst = g_raw_ref;
  } else {
    dst = g_raw_lr;
  }
  dst += (size_t)r * 288;
  #pragma unroll
  for (int j = 0; j < 5; j++) {
    int f = lane + j * 32;
    if (f < KD) {
      uint16_t h, lo;
      f16_split(v[j], h, lo);
      dst[f]       = h;
      dst[144 + f] = lo;
    }
  }
}

// ------------------------------- pack into m16n8k16 fragment layouts --------
__global__ __launch_bounds__(256) void pack_kernel() {
  int ti  = blockIdx.x;                  // b*NT + tile
  int isB = blockIdx.y;
  const uint32_t* raw32 = reinterpret_cast<const uint32_t*>(
      (isB ? g_raw_ref : g_raw_lr) + (size_t)ti * 128 * 288);
  uint4* dst = reinterpret_cast<uint4*>(
      (isB ? g_B : g_A) + (size_t)ti * TILE_U32);
  for (int o4 = threadIdx.x; o4 < TILE_U32 / 4; o4 += 256) {
    int kb = o4 >> 8, rr = o4 & 255;     // 256 uint4 per 4KB block
    uint4 val;
    if (isB) {
      int c2 = rr & 1, n = rr >> 1;
      int q = n * 144 + kb * 8 + 2 * c2;
      val.x = raw32[q];     val.y = raw32[q + 4];
      val.z = raw32[q + 1]; val.w = raw32[q + 5];
    } else {
      int c = rr & 3, g = (rr >> 2) & 7, mg = rr >> 5;
      int m = mg * 16 + g;
      int q = kb * 8 + c;
      val.x = raw32[m * 144 + q];       val.y = raw32[(m + 8) * 144 + q];
      val.z = raw32[m * 144 + q + 4];   val.w = raw32[(m + 8) * 144 + q + 4];
    }
    dst[o4] = val;
  }
}

// ------------------------------------------- argmax GEMM via mma.sync -------
#define SM_A   0          /* 73728 B: resident A tile image (18 blocks) */
#define SM_B   73728      /* ring: 8 x 4096 B */
#define SM_MB  106496     /* mbarriers: 8 full + 8 empty */
#define SM_RV  106752     /* 2048 B reduce vals (4 x 128) */
#define SM_RI  108800     /* 2048 B reduce idx  */
#define SMEM_TOTAL 110848

__global__ __launch_bounds__(384, 1) void argmax_mma(
    float* __restrict__ out_tail, int write_tail) {
  extern __shared__ __align__(16) char smem[];
  uint32_t sb = smem_u32(smem);
  int tid = threadIdx.x, wid = tid >> 5, lane = tid & 31;
  int cta = blockIdx.x;
  int b = cta / NT, qt = cta - b * NT;
  const uint32_t* Atile = g_A + (size_t)cta * TILE_U32;
  const uint32_t* Bbase = g_B + (size_t)b * NT * TILE_U32;

  uint32_t mb_full  = sb + SM_MB;        // 8 x 8B
  uint32_t mb_empty = sb + SM_MB + 64;   // 8 x 8B
  if (tid == 0) {
    for (int s = 0; s < 8; s++) {
      mbar_init(mb_full + 8 * s, 32);
      mbar_init(mb_empty + 8 * s, 256);  // 8 compute warps x 32 lanes
    }
  }
  // resident A image: contiguous 73728 B
  for (int c = tid; c < TILE_U32 / 4; c += 384)
    cp16(sb + SM_A + c * 16, Atile + c * 4);
  cp_commit();
  cp_wait0();
  __syncthreads();

  if (wid >= 8) {
    // ---- producers: 4 warps, gblk % 4 == pw, slot = gblk & 7 ----
    int pw = wid - 8;
    for (int gblk = pw; gblk < NT * NKB; gblk += 4) {
      int s = gblk & 7, u = gblk >> 3;
      mbar_wait(mb_empty + 8 * s, (u & 1) ^ 1);
      const uint32_t* src = Bbase + (size_t)gblk * 1024;
      uint32_t slot = sb + SM_B + s * 4096;
      #pragma unroll
      for (int i = 0; i < 8; i++) {
        int c = i * 32 + lane;
        cp16(slot + c * 16, src + c * 4);
      }
      cp_commit();
      cp_wait0();
      mbar_arrive(mb_full + 8 * s);
    }
  } else {
    // ---- compute warps: 2x4 grid of 64x32 warp tiles (2 warps / SMSP) ----
    int wm = wid & 1, wn = (wid >> 1) & 3;
    float C[4][4][4];          // hi*hi, fp32 accumulate
    uint32_t Cx[4][4][2];      // cross terms, fp16 accumulate (f16x2 regs)
    float bestv[8];
    int besti[8];
    #pragma unroll
    for (int i = 0; i < 8; i++) { bestv[i] = -3.4e38f; besti[i] = 0; }

    uint32_t abase = sb + SM_A + (lane >> 2) * 64 + (lane & 3) * 16;
    uint32_t bbase = sb + SM_B + wn * 1024 + (lane >> 2) * 32 + (lane & 3) * 8;

    for (int t = 0; t < NT; t++) {
      #pragma unroll
      for (int mf = 0; mf < 4; mf++)
        #pragma unroll
        for (int nf = 0; nf < 4; nf++) {
          #pragma unroll
          for (int c = 0; c < 4; c++) C[mf][nf][c] = 0.f;
          Cx[mf][nf][0] = 0u; Cx[mf][nf][1] = 0u;
        }

      for (int kb = 0; kb < NKB; kb++) {
        int gblk = t * NKB + kb, s = gblk & 7, u = gblk >> 3;
        mbar_wait(mb_full + 8 * s, u & 1);
        uint32_t bslot = bbase + s * 4096;
        uint32_t breg[4][2];
        #pragma unroll
        for (int nf = 0; nf < 4; nf++)
          asm volatile("ld.shared.v2.b32 {%0,%1}, [%2];"
                       : "=r"(breg[nf][0]), "=r"(breg[nf][1])
                       : "r"(bslot + nf * 256));
        if (kb < 9) {
          // B = ref-hi: A-hi -> C (f32), A-lo -> Cx (f16)
          uint32_t areg[4][4];
          #pragma unroll
          for (int mf = 0; mf < 4; mf++)
            asm volatile("ld.shared.v4.b32 {%0,%1,%2,%3}, [%4];"
                         : "=r"(areg[mf][0]), "=r"(areg[mf][1]),
                           "=r"(areg[mf][2]), "=r"(areg[mf][3])
                         : "r"(abase + kb * 4096 + (wm * 4 + mf) * 512));
          #pragma unroll
          for (int mf = 0; mf < 4; mf++)
            #pragma unroll
            for (int nf = 0; nf < 4; nf++)
              mma_f16(C[mf][nf], areg[mf], breg[nf]);
          uint32_t areg2[4][4];
          #pragma unroll
          for (int mf = 0; mf < 4; mf++)
            asm volatile("ld.shared.v4.b32 {%0,%1,%2,%3}, [%4];"
                         : "=r"(areg2[mf][0]), "=r"(areg2[mf][1]),
                           "=r"(areg2[mf][2]), "=r"(areg2[mf][3])
                         : "r"(abase + (kb + 9) * 4096 + (wm * 4 + mf) * 512));
          #pragma unroll
          for (int mf = 0; mf < 4; mf++)
            #pragma unroll
            for (int nf = 0; nf < 4; nf++)
              mma_f16acc(Cx[mf][nf], areg2[mf], breg[nf]);
        } else {
          // B = ref-lo: A-hi -> Cx (f16)
          int ab = kb - 9;
          uint32_t areg[4][4];
          #pragma unroll
          for (int mf = 0; mf < 4; mf++)
            asm volatile("ld.shared.v4.b32 {%0,%1,%2,%3}, [%4];"
                         : "=r"(areg[mf][0]), "=r"(areg[mf][1]),
                           "=r"(areg[mf][2]), "=r"(areg[mf][3])
                         : "r"(abase + ab * 4096 + (wm * 4 + mf) * 512));
          #pragma unroll
          for (int mf = 0; mf < 4; mf++)
            #pragma unroll
            for (int nf = 0; nf < 4; nf++)
              mma_f16acc(Cx[mf][nf], areg[mf], breg[nf]);
        }
        mbar_arrive(mb_empty + 8 * s);
      }
      // running argmax (strict > keeps lowest index; n ascends in iteration)
      #pragma unroll
      for (int mf = 0; mf < 4; mf++) {
        #pragma unroll
        for (int h = 0; h < 2; h++) {
          int slot = mf * 2 + h;
          #pragma unroll
          for (int nf = 0; nf < 4; nf++) {
            #pragma unroll
            for (int cl = 0; cl < 2; cl++) {
              float vv = C[mf][nf][h * 2 + cl] +
                         f16bits_to_f32(Cx[mf][nf][h] >> (16 * cl));
              int n = t * 128 + wn * 32 + nf * 8 + (lane & 3) * 2 + cl;
              if (vv > bestv[slot]) { bestv[slot] = vv; besti[slot] = n; }
            }
          }
        }
      }
    }
    // reduce across quad lanes (same m rows)
    #pragma unroll
    for (int slot = 0; slot < 8; slot++) {
      float v = bestv[slot];
      int i = besti[slot];
      #pragma unroll
      for (int off = 1; off <= 2; off <<= 1) {
        float ov = __shfl_xor_sync(0xffffffffu, v, off);
        int oi = __shfl_xor_sync(0xffffffffu, i, off);
        if (ov > v || (ov == v && oi < i)) { v = ov; i = oi; }
      }
      bestv[slot] = v; besti[slot] = i;
    }
    if ((lane & 3) == 0) {
      float* rv = reinterpret_cast<float*>(smem + SM_RV);
      int* ri = reinterpret_cast<int*>(smem + SM_RI);
      #pragma unroll
      for (int slot = 0; slot < 8; slot++) {
        int m_local = wm * 64 + (slot >> 1) * 16 + (slot & 1) * 8 + (lane >> 2);
        rv[wn * 128 + m_local] = bestv[slot];
        ri[wn * 128 + m_local] = besti[slot];
      }
    }
  }

  __syncthreads();
  if (tid < 128) {
    const float* rv = reinterpret_cast<const float*>(smem + SM_RV);
    const int* ri = reinterpret_cast<const int*>(smem + SM_RI);
    float best = -3.4e38f; int bi = 0x7fffffff;
    #pragma unroll
    for (int wn = 0; wn < 4; wn++) {
      float v = rv[wn * 128 + tid];
      int i = ri[wn * 128 + tid];
      if (v > best || (v == best && i < bi)) { best = v; bi = i; }
    }
    g_S[b * LQ + qt * 128 + tid] = bi;
    if (write_tail) out_tail[b * LQ + qt * 128 + tid] = (float)bi;
  }
}

// ----------------------------------------------- gather + fold (fused) ------
__global__ __launch_bounds__(256) void fold_kernel(
    const float* __restrict__ org, float* __restrict__ out) {
  int b = blockIdx.z;
  int x = blockIdx.x * 16 + threadIdx.x;
  int y = blockIdx.y * 16 + threadIdx.y;
  int yp = y + 2, xp = x + 2;
  int myl = max(0, (yp - 4) / 2);
  int myh = min(95, yp >> 1);
  int mxl = max(0, (xp - 4) / 2);
  int mxh = min(95, xp >> 1);
  const int* Sb = g_S + b * LQ;

  int off[9];
  #pragma unroll
  for (int a = 0; a < 3; a++) {
    int my = myl + a;
    bool mok = (my <= myh);
    int myc = min(my, 95);
    int ki = yp - 2 * my;
    #pragma unroll
    for (int e = 0; e < 3; e++) {
      int mx = mxl + e;
      bool xok = (mx <= mxh);
      int mxc = min(mx, 95);
      int kj = xp - 2 * mx;
      int s = Sb[myc * 96 + mxc];
      int sy = s / 96;
      int sx = s - sy * 96;
      int gy = 2 * sy + ki - 2;
      int gx = 2 * sx + kj - 2;
      bool inb = mok & xok & (gy >= 0) & (gy < 192) & (gx >= 0) & (gx < 192);
      off[a * 3 + e] = inb ? (gy * 192 + gx) : -1;
    }
  }

  #pragma unroll 4
  for (int c = 0; c < 16; c++) {
    const float* oc = org + (size_t)((b * 16 + c) * 192) * 192;
    float sum = 0.f;
    #pragma unroll
    for (int u = 0; u < 9; u++)
      if (off[u] >= 0) sum += oc[off[u]];
    out[((b * 16 + c) * 192 + y) * 192 + x] = sum;
  }
}

// ------------------------------------------------------------------ host ----
extern "C" void kernel_launch(void* const* d_in, const int* in_sizes, int n_in,
                              void* d_out, int out_size) {
  (void)in_sizes; (void)n_in;
  const float* lrsr  = (const float*)d_in[0];
  const float* refsr = (const float*)d_in[1];
  const float* org   = (const float*)d_in[2];
  float* out = (float*)d_out;

  cudaFuncSetAttribute(argmax_mma, cudaFuncAttributeMaxDynamicSharedMemorySize,
                       SMEM_TOTAL);

  prep_kernel<<<(2 * BB * LQ * 32) / 256, 256>>>(lrsr, refsr);
  pack_kernel<<<dim3(BB * NT, 2), 256>>>();
  int write_tail = (out_size >= TOUT + SOUT) ? 1 : 0;
  argmax_mma<<<BB * NT, 384, SMEM_TOTAL>>>(out + TOUT, write_tail);
  fold_kernel<<<dim3(12, 12, BB), dim3(16, 16)>>>(org, out);
}